// round 1
// baseline (speedup 1.0000x reference)
#include <cuda_runtime.h>
#include <math_constants.h>

// ChamferLoss: out = 0.7 * mean_b[chamfer(pf,gf)] + 0.3 * mean_b[chamfer(pn,gn)]
// chamfer(p,q) = mean_i min_j d2(p_i,q_j) + mean_j min_i d2(q_j,p_i)
//
// Strategy: d2 = |p|^2 + |q|^2 - 2 p.q  (same expansion as reference)
//           min_j d2 = |p|^2 - 2 * max_j ( p.q - 0.5*|q|^2 )
// Inner loop per pair: 1 LDS.128 (broadcast) + 3 FMA + 1 FMNMX.
// One fused kernel covers all 4 (set, direction) jobs for full-chip occupancy.

#define TILE 1024   // q-points per shared tile (16 KB of float4)
#define BLK  128    // threads per block (p-points per block)

// Work-unit layout (blockIdx.x):
//   [0,256)   : nonfiltered, dir pn->gn   (4 batches x 64 chunks)
//   [256,512) : nonfiltered, dir gn->pn
//   [512,640) : filtered,    dir pf->gf   (4 batches x 32 chunks)
//   [640,768) : filtered,    dir gf->pf
#define GRID 768

__global__ void zero_out_kernel(float* out) {
    if (threadIdx.x == 0) out[0] = 0.0f;
}

__global__ __launch_bounds__(BLK) void chamfer_fused_kernel(
    const float* __restrict__ pf, const float* __restrict__ gf,
    const float* __restrict__ pn, const float* __restrict__ gn,
    float* __restrict__ out)
{
    const int u = blockIdx.x;
    const float* P;
    const float* Q;
    int   NM;     // points per cloud (N == M for both sets here)
    float scale;  // weight / (B * N)
    int   b, chunk;

    if (u < 512) {
        NM    = 8192;
        scale = 0.3f / (4.0f * 8192.0f);
        if (u < 256) { P = pn; Q = gn; } else { P = gn; Q = pn; }
        const int v = u & 255;
        b = v >> 6;          // 64 chunks of 128 p-points each
        chunk = v & 63;
    } else {
        NM    = 4096;
        scale = 0.7f / (4.0f * 4096.0f);
        const int w = u - 512;
        if (w < 128) { P = pf; Q = gf; } else { P = gf; Q = pf; }
        const int v = w & 127;
        b = v >> 5;          // 32 chunks of 128 p-points each
        chunk = v & 31;
    }

    const float* Pb = P + (size_t)b * NM * 3;
    const float* Qb = Q + (size_t)b * NM * 3;

    const int i = chunk * BLK + threadIdx.x;   // always < NM by construction
    const float px = Pb[3 * i + 0];
    const float py = Pb[3 * i + 1];
    const float pz = Pb[3 * i + 2];
    const float p2 = fmaf(px, px, fmaf(py, py, pz * pz));

    __shared__ float4 sq[TILE];

    // 4 independent running maxima to break the FMNMX dependency chain
    float m0 = -CUDART_INF_F, m1 = m0, m2 = m0, m3 = m0;

    for (int t = 0; t < NM; t += TILE) {
        __syncthreads();   // protect sq from previous iteration's readers
        #pragma unroll
        for (int j = threadIdx.x; j < TILE; j += BLK) {
            const float* q = Qb + 3 * (t + j);
            const float qx = q[0], qy = q[1], qz = q[2];
            sq[j] = make_float4(qx, qy, qz,
                                0.5f * fmaf(qx, qx, fmaf(qy, qy, qz * qz)));
        }
        __syncthreads();

        #pragma unroll 4
        for (int j = 0; j < TILE; j += 4) {
            const float4 q0 = sq[j + 0];
            const float4 q1 = sq[j + 1];
            const float4 q2 = sq[j + 2];
            const float4 q3 = sq[j + 3];
            m0 = fmaxf(m0, fmaf(px, q0.x, fmaf(py, q0.y, fmaf(pz, q0.z, -q0.w))));
            m1 = fmaxf(m1, fmaf(px, q1.x, fmaf(py, q1.y, fmaf(pz, q1.z, -q1.w))));
            m2 = fmaxf(m2, fmaf(px, q2.x, fmaf(py, q2.y, fmaf(pz, q2.z, -q2.w))));
            m3 = fmaxf(m3, fmaf(px, q3.x, fmaf(py, q3.y, fmaf(pz, q3.z, -q3.w))));
        }
    }

    const float smax = fmaxf(fmaxf(m0, m1), fmaxf(m2, m3));
    const float d2   = fmaf(-2.0f, smax, p2);  // min squared distance
    float val = d2 * scale;

    // block reduction: warp shuffle, then cross-warp via shared
    #pragma unroll
    for (int o = 16; o; o >>= 1)
        val += __shfl_down_sync(0xffffffffu, val, o);

    __shared__ float ws[BLK / 32];
    if ((threadIdx.x & 31) == 0) ws[threadIdx.x >> 5] = val;
    __syncthreads();
    if (threadIdx.x == 0) {
        float s = 0.0f;
        #pragma unroll
        for (int w = 0; w < BLK / 32; w++) s += ws[w];
        atomicAdd(out, s);
    }
}

extern "C" void kernel_launch(void* const* d_in, const int* in_sizes, int n_in,
                              void* d_out, int out_size) {
    const float* pf = (const float*)d_in[0];  // pred_filtered    [4,4096,3]
    const float* gf = (const float*)d_in[1];  // gt_filtered      [4,4096,3]
    const float* pn = (const float*)d_in[2];  // pred_nonfiltered [4,8192,3]
    const float* gn = (const float*)d_in[3];  // gt_nonfiltered   [4,8192,3]
    float* out = (float*)d_out;

    zero_out_kernel<<<1, 32>>>(out);
    chamfer_fused_kernel<<<GRID, BLK>>>(pf, gf, pn, gn, out);
}

// round 2
// speedup vs baseline: 1.6600x; 1.6600x over previous
#include <cuda_runtime.h>
#include <math_constants.h>

// ChamferLoss: out = 0.7*mean_b[chamfer(pf,gf)] + 0.3*mean_b[chamfer(pn,gn)]
// min_j d2(p,q_j) = |p|^2 - 2 * max_j ( p.q_j - 0.5|q_j|^2 )
//
// Pass 1: 640 uniform blocks, each 1024 p-points x 1024 q-points (1M pairs).
//         Inner math in packed f32x2 FMAs (FFMA2): 3 FFMA2 per 2 pairs.
//         q tile pre-duplicated in shared (32B/q) -> 2 LDS.128 per q per thread
//         serving 8 p-points. Per-(p, q-slice) max written to global scratch.
// Pass 2: combine slice maxima per p, form d2, scale, reduce-sum into out[0].

#define BLK 128
#define PPT 8               // p-points per thread
#define PPB (BLK * PPT)     // 1024 p-points per block
#define QT  1024            // q-points per slice (32KB shared)

// nonfiltered: 2 dir * 4 b * 8 p-chunks * 8 q-slices = 512 blocks
// filtered:    2 dir * 4 b * 4 p-chunks * 4 q-slices = 128 blocks
#define NF_BLOCKS 512
#define GRID 640

#define NF_PART (2 * 4 * 8192 * 8)   // 524288 partials
#define F_PART  (2 * 4 * 4096 * 4)   // 131072 partials
__device__ float g_partial[NF_PART + F_PART];

typedef unsigned long long ull;

__device__ __forceinline__ ull fma2(ull a, ull b, ull c) {
    ull d;
    asm("fma.rn.f32x2 %0, %1, %2, %3;" : "=l"(d) : "l"(a), "l"(b), "l"(c));
    return d;
}
__device__ __forceinline__ ull pack2(float lo, float hi) {
    ull d;
    asm("mov.b64 %0, {%1, %2};" : "=l"(d) : "f"(lo), "f"(hi));
    return d;
}
__device__ __forceinline__ float2 unpack2(ull v) {
    float2 r;
    asm("mov.b64 {%0, %1}, %2;" : "=f"(r.x), "=f"(r.y) : "l"(v));
    return r;
}

__global__ void zero_out_kernel(float* out) {
    if (threadIdx.x == 0) out[0] = 0.0f;
}

__global__ __launch_bounds__(BLK) void chamfer_pass1(
    const float* __restrict__ pf, const float* __restrict__ gf,
    const float* __restrict__ pn, const float* __restrict__ gn)
{
    const int u = blockIdx.x;
    const float* P;
    const float* Q;
    int pc, qs, S;
    long scr_row;   // scratch base row (points) incl. region offset scaling below

    if (u < NF_BLOCKS) {
        int v = u;
        qs = v & 7;  v >>= 3;
        pc = v & 7;  v >>= 3;
        const int b = v & 3;
        const int dir = v >> 2;
        P = (dir ? gn : pn) + (size_t)b * 8192 * 3;
        Q = (dir ? pn : gn) + (size_t)b * 8192 * 3;
        S = 8;
        scr_row = (long)(dir * 4 + b) * 8192;
    } else {
        int v = u - NF_BLOCKS;
        qs = v & 3;  v >>= 2;
        pc = v & 3;  v >>= 2;
        const int b = v & 3;
        const int dir = v >> 2;
        P = (dir ? gf : pf) + (size_t)b * 4096 * 3;
        Q = (dir ? pf : gf) + (size_t)b * 4096 * 3;
        S = 4;
        scr_row = (long)(dir * 4 + b) * 4096;
    }

    // shared q tile: s_q[2j] = {(qx,qx),(qy,qy)}, s_q[2j+1] = {(qz,qz),(nh,nh)}
    __shared__ ulonglong2 s_q[QT * 2];

    for (int j = threadIdx.x; j < QT; j += BLK) {
        const float* q = Q + 3 * (qs * QT + j);
        const float qx = q[0], qy = q[1], qz = q[2];
        const float nh = -0.5f * fmaf(qx, qx, fmaf(qy, qy, qz * qz));
        ulonglong2 a, bb;
        a.x  = pack2(qx, qx);
        a.y  = pack2(qy, qy);
        bb.x = pack2(qz, qz);
        bb.y = pack2(nh, nh);
        s_q[2 * j]     = a;
        s_q[2 * j + 1] = bb;
    }

    // load 8 p-points (4 packed pairs), strided by BLK for coalescing
    const int pbase = pc * PPB + threadIdx.x;
    ull X[4], Y[4], Z[4];
    #pragma unroll
    for (int k = 0; k < 4; k++) {
        const int i0 = pbase + (2 * k) * BLK;
        const int i1 = pbase + (2 * k + 1) * BLK;
        X[k] = pack2(P[3 * i0 + 0], P[3 * i1 + 0]);
        Y[k] = pack2(P[3 * i0 + 1], P[3 * i1 + 1]);
        Z[k] = pack2(P[3 * i0 + 2], P[3 * i1 + 2]);
    }

    float m[8];
    #pragma unroll
    for (int k = 0; k < 8; k++) m[k] = -CUDART_INF_F;

    __syncthreads();

    #pragma unroll 8
    for (int j = 0; j < QT; j++) {
        const ulonglong2 a  = s_q[2 * j];
        const ulonglong2 bb = s_q[2 * j + 1];
        #pragma unroll
        for (int k = 0; k < 4; k++) {
            const ull t = fma2(X[k], a.x, fma2(Y[k], a.y, fma2(Z[k], bb.x, bb.y)));
            const float2 f = unpack2(t);
            m[2 * k]     = fmaxf(m[2 * k],     f.x);
            m[2 * k + 1] = fmaxf(m[2 * k + 1], f.y);
        }
    }

    // write per-(p, slice) partial maxima
    const long region = (u < NF_BLOCKS) ? 0 : NF_PART;
    #pragma unroll
    for (int k = 0; k < 8; k++) {
        const int i = pc * PPB + k * BLK + threadIdx.x;   // point index in cloud
        g_partial[region + (scr_row + i) * S + qs] = m[k];
    }
}

__global__ __launch_bounds__(256) void chamfer_pass2(
    const float* __restrict__ pf, const float* __restrict__ gf,
    const float* __restrict__ pn, const float* __restrict__ gn,
    float* __restrict__ out)
{
    const int t = blockIdx.x * 256 + threadIdx.x;   // 98304 total

    const float* P;
    int i, S;
    long base;
    float scale;
    if (t < 65536) {
        const int grp = t >> 13;        // dir*4 + b
        i = t & 8191;
        const int dir = grp >> 2, b = grp & 3;
        P = (dir ? gn : pn) + (size_t)b * 8192 * 3;
        base = (long)t * 8;
        S = 8;
        scale = 0.3f / (4.0f * 8192.0f);
    } else {
        const int tf = t - 65536;
        const int grp = tf >> 12;
        i = tf & 4095;
        const int dir = grp >> 2, b = grp & 3;
        P = (dir ? gf : pf) + (size_t)b * 4096 * 3;
        base = NF_PART + (long)tf * 4;
        S = 4;
        scale = 0.7f / (4.0f * 4096.0f);
    }

    float mx = -CUDART_INF_F;
    for (int s = 0; s < S; s++) mx = fmaxf(mx, g_partial[base + s]);

    const float px = P[3 * i], py = P[3 * i + 1], pz = P[3 * i + 2];
    const float p2 = fmaf(px, px, fmaf(py, py, pz * pz));
    float val = fmaf(-2.0f, mx, p2) * scale;

    #pragma unroll
    for (int o = 16; o; o >>= 1)
        val += __shfl_down_sync(0xffffffffu, val, o);

    __shared__ float ws[8];
    if ((threadIdx.x & 31) == 0) ws[threadIdx.x >> 5] = val;
    __syncthreads();
    if (threadIdx.x == 0) {
        float s = 0.0f;
        #pragma unroll
        for (int w = 0; w < 8; w++) s += ws[w];
        atomicAdd(out, s);
    }
}

extern "C" void kernel_launch(void* const* d_in, const int* in_sizes, int n_in,
                              void* d_out, int out_size) {
    const float* pf = (const float*)d_in[0];  // pred_filtered    [4,4096,3]
    const float* gf = (const float*)d_in[1];  // gt_filtered      [4,4096,3]
    const float* pn = (const float*)d_in[2];  // pred_nonfiltered [4,8192,3]
    const float* gn = (const float*)d_in[3];  // gt_nonfiltered   [4,8192,3]
    float* out = (float*)d_out;

    zero_out_kernel<<<1, 32>>>(out);
    chamfer_pass1<<<GRID, BLK>>>(pf, gf, pn, gn);
    chamfer_pass2<<<98304 / 256, 256>>>(pf, gf, pn, gn, out);
}